// round 5
// baseline (speedup 1.0000x reference)
#include <cuda_runtime.h>
#include <cuda_bf16.h>
#include <math.h>

#define N_USER 100000
#define N_ITEM 60000
#define NN     160000      // total nodes
#define NNZ_E  2000000
#define BB     16384
#define DD     64

typedef unsigned long long u64;

// ---------------- device scratch (static, allocation-free) ----------------
__device__ float g_ego [(size_t)NN * DD];        // 41 MB
__device__ float g_side[(size_t)NN * DD];        // 41 MB
__device__ float g_alle[(size_t)NN * 4 * DD];    // 164 MB  [node][256]
__device__ int   g_cnt   [NN];                   // zeroed by k_scan each exec
__device__ int   g_off   [NN + 1];
__device__ int   g_cursor[NN];
__device__ int2  g_cv    [NNZ_E];                // packed (col, val-bits)

// ---------------- f32x2 packed helpers -------------------------------------
__device__ __forceinline__ u64 pack2(float x, float y) {
    u64 r;
    asm("mov.b64 %0, {%1, %2};" : "=l"(r) : "f"(x), "f"(y));
    return r;
}
__device__ __forceinline__ float2 unpack2(u64 v) {
    float2 r;
    asm("mov.b64 {%0, %1}, %2;" : "=f"(r.x), "=f"(r.y) : "l"(v));
    return r;
}
__device__ __forceinline__ void ffma2(u64& d, u64 a, u64 b) {
    asm("fma.rn.f32x2 %0, %1, %2, %0;" : "+l"(d) : "l"(a), "l"(b));
}

// ------- fused init + hist: g_cnt is zero on entry (BSS / k_scan post-zero)
__global__ void k_inithist(const float* __restrict__ ue, const float* __restrict__ ie,
                           const int* __restrict__ rows) {
    int idx = blockIdx.x * blockDim.x + threadIdx.x;
    if (idx < NN * DD / 4) {
        int fidx = idx << 2;
        int node = fidx >> 6;
        int d    = fidx & 63;
        float4 v = (node < N_USER) ? ((const float4*)ue)[idx]
                                   : *(const float4*)&ie[fidx - N_USER * DD];
        *(float4*)&g_ego[fidx] = v;
        *(float4*)&g_alle[(size_t)node * 256 + d] = v;
    }
    if (idx < NNZ_E) atomicAdd(&g_cnt[rows[idx]], 1);
}

// single-block exclusive scan over g_cnt -> g_off, g_cursor; re-zeroes g_cnt
__global__ void k_scan() {
    const int CH = (NN + 1023) >> 10;   // 157
    int t = threadIdx.x;
    int b0 = t * CH;
    int b1 = b0 + CH; if (b1 > NN) b1 = NN;
    if (b0 > NN) b0 = NN;

    int s = 0;
    for (int i = b0; i < b1; i++) s += g_cnt[i];

    __shared__ int wsum[32];
    int lane = t & 31, wid = t >> 5;
    int v = s;
    #pragma unroll
    for (int o = 1; o < 32; o <<= 1) {
        int u = __shfl_up_sync(0xffffffffu, v, o);
        if (lane >= o) v += u;
    }
    if (lane == 31) wsum[wid] = v;
    __syncthreads();
    if (wid == 0) {
        int w = wsum[lane];
        #pragma unroll
        for (int o = 1; o < 32; o <<= 1) {
            int u = __shfl_up_sync(0xffffffffu, w, o);
            if (lane >= o) w += u;
        }
        wsum[lane] = w;  // inclusive warp sums
    }
    __syncthreads();
    int excl = v - s + (wid > 0 ? wsum[wid - 1] : 0);
    int off = excl;
    for (int i = b0; i < b1; i++) {
        g_off[i] = off;
        g_cursor[i] = off;
        int c = g_cnt[i];
        g_cnt[i] = 0;            // ready for next graph replay
        off += c;
    }
    if (t == 1023) g_off[NN] = off;   // == NNZ_E
}

__global__ void k_fill(const int* __restrict__ rows, const int* __restrict__ cols,
                       const float* __restrict__ vals) {
    int e = blockIdx.x * blockDim.x + threadIdx.x;
    if (e < NNZ_E) {
        int r = rows[e];
        int p = atomicAdd(&g_cursor[r], 1);
        g_cv[p] = make_int2(cols[e], __float_as_int(vals[e]));
    }
}

// ---------------- SpMM: warp per row, half-warp per edge stream, 2 edges/iter
// side[r] = sum_e val*ego[col].  16 lanes x float4 cover one ego row (256B).
__global__ void k_spmm() {
    int w = (blockIdx.x * blockDim.x + threadIdx.x) >> 5;
    if (w >= NN) return;
    int lane = threadIdx.x & 31;
    int half = lane >> 4;          // edge-stream parity
    int q4   = (lane & 15) << 2;   // float4 column offset
    int s = g_off[w], e = g_off[w + 1];
    u64 a01 = 0, a23 = 0;
    int idx = s + half;
    // two edges in flight per half-warp (stride-2 stream, 2 at a time)
    for (; idx + 2 < e; idx += 4) {
        int2 cvA = g_cv[idx];
        int2 cvB = g_cv[idx + 2];
        const u64* pA = (const u64*)&g_ego[(size_t)cvA.x * DD + q4];
        const u64* pB = (const u64*)&g_ego[(size_t)cvB.x * DD + q4];
        u64 gA0 = pA[0], gA1 = pA[1];
        u64 gB0 = pB[0], gB1 = pB[1];
        float vA = __int_as_float(cvA.y);
        float vB = __int_as_float(cvB.y);
        u64 vA2 = pack2(vA, vA), vB2 = pack2(vB, vB);
        ffma2(a01, vA2, gA0); ffma2(a23, vA2, gA1);
        ffma2(a01, vB2, gB0); ffma2(a23, vB2, gB1);
    }
    if (idx < e) {
        int2 cv = g_cv[idx];
        float v = __int_as_float(cv.y);
        u64 v2 = pack2(v, v);
        const u64* pg = (const u64*)&g_ego[(size_t)cv.x * DD + q4];
        u64 g0 = pg[0], g1 = pg[1];
        ffma2(a01, v2, g0);
        ffma2(a23, v2, g1);
    }
    float2 p01 = unpack2(a01), p23 = unpack2(a23);
    float ax = p01.x, ay = p01.y, az = p23.x, aw = p23.y;
    ax += __shfl_xor_sync(0xffffffffu, ax, 16);
    ay += __shfl_xor_sync(0xffffffffu, ay, 16);
    az += __shfl_xor_sync(0xffffffffu, az, 16);
    aw += __shfl_xor_sync(0xffffffffu, aw, 16);
    if (half == 0) {
        float4 o; o.x = ax; o.y = ay; o.z = az; o.w = aw;
        *(float4*)&g_side[(size_t)w * DD + q4] = o;
    }
}

// ---------------- transform -------------------------------------------------
// block = 128 thr = 4 warps covers 128 rows. warp w = colgroup (16 cols);
// lane owns 4 rows: lane, lane+32, lane+64, lane+96. W cached in shared
// (uniform LDS.64 broadcast, amortized over 4 rows). acc in packed f32x2.
// dynamic smem floats: sS[128][65], sE[128][65], sWg[4096], sWb[4096],
//                      sP[4][128], sInv[128]
#define TR_SMEM_FLOATS (128*65 + 128*65 + 4096 + 4096 + 4*128 + 128)
__global__ void k_transform(const float* __restrict__ Wg, const float* __restrict__ bg,
                            const float* __restrict__ Wb, const float* __restrict__ bb,
                            int layer) {
    extern __shared__ float smem[];
    float (*sS)[65] = (float(*)[65])smem;
    float (*sE)[65] = (float(*)[65])(smem + 128 * 65);
    float* sWg = smem + 2 * 128 * 65;
    float* sWb = sWg + 4096;
    float* sP  = sWb + 4096;        // [4][128]
    float* sInv = sP + 4 * 128;     // [128]

    int r0 = blockIdx.x * 128;
    int t = threadIdx.x;
    int w = t >> 5, lane = t & 31;

    // stage side/ego tiles (128 rows x 64 cols)
    for (int i = t; i < 2048; i += 128) {
        int rr = i >> 4, c4 = (i & 15) << 2;
        float4 a = *(const float4*)&g_side[(size_t)(r0 + rr) * DD + c4];
        float4 b = *(const float4*)&g_ego [(size_t)(r0 + rr) * DD + c4];
        sS[rr][c4] = a.x; sS[rr][c4+1] = a.y; sS[rr][c4+2] = a.z; sS[rr][c4+3] = a.w;
        sE[rr][c4] = b.x; sE[rr][c4+1] = b.y; sE[rr][c4+2] = b.z; sE[rr][c4+3] = b.w;
    }
    // stage W (two 64x64 matrices for this layer)
    for (int i = t; i < 1024; i += 128) {
        ((float4*)sWg)[i] = ((const float4*)(Wg + layer * 4096))[i];
        ((float4*)sWb)[i] = ((const float4*)(Wb + layer * 4096))[i];
    }
    __syncthreads();

    int j0 = w * 16;

    u64 acc[4][8];
    {
        u64 binit[8];
        #pragma unroll
        for (int v = 0; v < 8; v++) {
            float bx = bg[layer * 64 + j0 + 2*v]     + bb[layer * 64 + j0 + 2*v];
            float by = bg[layer * 64 + j0 + 2*v + 1] + bb[layer * 64 + j0 + 2*v + 1];
            binit[v] = pack2(bx, by);
        }
        #pragma unroll
        for (int m = 0; m < 4; m++)
            #pragma unroll
            for (int v = 0; v < 8; v++) acc[m][v] = binit[v];
    }

    #pragma unroll 2
    for (int i = 0; i < 64; i++) {
        u64 sp[4], bp[4];
        #pragma unroll
        for (int m = 0; m < 4; m++) {
            int r = lane + 32 * m;
            float sm = sS[r][i];
            float bm = sE[r][i] * sm;
            sp[m] = pack2(sm, sm);
            bp[m] = pack2(bm, bm);
        }
        const u64* pg = (const u64*)&sWg[i * 64 + j0];   // uniform broadcast
        const u64* pb = (const u64*)&sWb[i * 64 + j0];
        #pragma unroll
        for (int v = 0; v < 8; v++) {
            u64 gg = pg[v], hh = pb[v];
            #pragma unroll
            for (int m = 0; m < 4; m++) {
                ffma2(acc[m][v], sp[m], gg);
                ffma2(acc[m][v], bp[m], hh);
            }
        }
    }

    // leaky relu + per-row sumsq partials (keep activations packed in acc)
    #pragma unroll
    for (int m = 0; m < 4; m++) {
        float ss = 0.f;
        #pragma unroll
        for (int v = 0; v < 8; v++) {
            float2 x = unpack2(acc[m][v]);
            x.x = (x.x > 0.f) ? x.x : 0.2f * x.x;
            x.y = (x.y > 0.f) ? x.y : 0.2f * x.y;
            acc[m][v] = pack2(x.x, x.y);
            ss = fmaf(x.x, x.x, fmaf(x.y, x.y, ss));
        }
        sP[w * 128 + lane + 32 * m] = ss;
    }
    __syncthreads();            // all reads of sS/sE and writes of sP done

    if (t < 128) {
        float tot = sP[t] + sP[128 + t] + sP[256 + t] + sP[384 + t];
        sInv[t] = 1.0f / fmaxf(sqrtf(tot), 1e-12f);
    }
    // stash activations into sE for coalesced writeback
    #pragma unroll
    for (int m = 0; m < 4; m++) {
        int r = lane + 32 * m;
        #pragma unroll
        for (int v = 0; v < 8; v++) {
            float2 x = unpack2(acc[m][v]);
            sE[r][j0 + 2*v]     = x.x;
            sE[r][j0 + 2*v + 1] = x.y;
        }
    }
    __syncthreads();

    for (int i = t; i < 2048; i += 128) {
        int rr = i >> 4, c4 = (i & 15) << 2;
        float inv = sInv[rr];
        float4 o;
        o.x = sE[rr][c4]; o.y = sE[rr][c4+1]; o.z = sE[rr][c4+2]; o.w = sE[rr][c4+3];
        *(float4*)&g_ego[(size_t)(r0 + rr) * DD + c4] = o;
        float4 n; n.x = o.x*inv; n.y = o.y*inv; n.z = o.z*inv; n.w = o.w*inv;
        *(float4*)&g_alle[(size_t)(r0 + rr) * 256 + (size_t)(layer + 1) * 64 + c4] = n;
    }
}

// ---------------- predict: warp per batch element -------------------------
__global__ void k_pred(const int* __restrict__ users, const int* __restrict__ items,
                       const float* __restrict__ pW, const float* __restrict__ pb,
                       float* __restrict__ out) {
    int w = (blockIdx.x * blockDim.x + threadIdx.x) >> 5;
    if (w >= BB) return;
    int lane = threadIdx.x & 31;
    size_t u = (size_t)users[w];
    size_t v = (size_t)N_USER + (size_t)items[w];
    const float* pu = &g_alle[u * 256 + lane * 8];
    const float* pv = &g_alle[v * 256 + lane * 8];
    const float* pw = pW + lane * 8;
    float acc = 0.f;
    #pragma unroll
    for (int q = 0; q < 8; q++) acc = fmaf(pu[q] * pv[q], pw[q], acc);
    #pragma unroll
    for (int o = 16; o > 0; o >>= 1) acc += __shfl_xor_sync(0xffffffffu, acc, o);
    if (lane == 0) out[w] = 1.0f / (1.0f + expf(-(acc + pb[0])));
}

// ---------------- launch ---------------------------------------------------
extern "C" void kernel_launch(void* const* d_in, const int* in_sizes, int n_in,
                              void* d_out, int out_size) {
    const int*   users = (const int*)  d_in[0];
    const int*   items = (const int*)  d_in[1];
    const int*   arows = (const int*)  d_in[2];
    const int*   acols = (const int*)  d_in[3];
    const float* avals = (const float*)d_in[4];
    const float* ue    = (const float*)d_in[5];
    const float* ie    = (const float*)d_in[6];
    const float* Wg    = (const float*)d_in[7];
    const float* bg    = (const float*)d_in[8];
    const float* Wb    = (const float*)d_in[9];
    const float* bb    = (const float*)d_in[10];
    const float* pW    = (const float*)d_in[11];
    const float* pb    = (const float*)d_in[12];
    float* out = (float*)d_out;

    const int tr_smem = TR_SMEM_FLOATS * 4;   // ~99.5 KB
    cudaFuncSetAttribute(k_transform, cudaFuncAttributeMaxDynamicSharedMemorySize, tr_smem);

    k_inithist<<<(NN * DD / 4 + 255) / 256, 256>>>(ue, ie, arows);
    k_scan<<<1, 1024>>>();
    k_fill<<<(NNZ_E + 255) / 256, 256>>>(arows, acols, avals);

    for (int k = 0; k < 3; k++) {
        k_spmm<<<NN / 8, 256>>>();                        // warp per row
        k_transform<<<NN / 128, 128, tr_smem>>>(Wg, bg, Wb, bb, k);
    }

    k_pred<<<(BB * 32) / 256, 256>>>(users, items, pW, pb, out);
}